// round 12
// baseline (speedup 1.0000x reference)
#include <cuda_runtime.h>
#include <cuda_bf16.h>
#include <math.h>

// ---------------------------------------------------------------------------
// SearchNet: cosine similarity top-k — SINGLE fused kernel
//   query [512] f32, database [N,512] f32 (N=500000), top_num=100
//   out: [values(K) | indices-as-float(K)] where K = out_size/2
//
//   Main body : keys = dot(q_raw,d)/|d| (= cos_sim*|q|, order-preserving);
//               lane 0 appends (key,idx) to a global list when
//               key > f2key(T0*|q|), T0=0.11 -> ~3200 candidates.
//   Epilogue  : LAST finishing block (threadfence+done counter) selects:
//               fast path: 2048-bin hist of candidates -> scan -> compact
//               survivors to smem -> exact m^2 rank -> write topK * 1/|q|.
//               fallback (arbitrary data): full hist/collect over g_keys.
//               Self-cleans all scratch (graph-replay invariant).
// ---------------------------------------------------------------------------

#define D 512
#define MAXN (1 << 20)        // >= 500000
#define CAND_CAP 16384
#define LST_CAP 1024          // compacted above-threshold list in smem
#define T0 0.11f

__device__ unsigned int g_keys[MAXN];
__device__ unsigned int g_ncand;      // zero at load; reset by epilogue
__device__ unsigned int g_done;       // zero at load; reset by epilogue
__device__ unsigned int g_fcnt;       // fallback collect counter
__device__ unsigned int g_cand_key[CAND_CAP];
__device__ unsigned int g_cand_idx[CAND_CAP];

// float -> order-preserving uint
__device__ __forceinline__ unsigned int f2key(float f) {
    unsigned int u = __float_as_uint(f);
    return (u & 0x80000000u) ? ~u : (u | 0x80000000u);
}
__device__ __forceinline__ float key2f(unsigned int k) {
    unsigned int u = (k & 0x80000000u) ? (k ^ 0x80000000u) : ~k;
    return __uint_as_float(u);
}

__global__ __launch_bounds__(256) void fused_kernel(
        const float* __restrict__ db, const float* __restrict__ q,
        float* __restrict__ out, int N, int K) {
    int t = threadIdx.x;
    int warp = (blockIdx.x * blockDim.x + t) >> 5;
    int lane = t & 31;
    int r0 = warp * 2;

    // ======================= sims body (unchanged) =========================
    if (r0 < N) {
        bool has1 = (r0 + 1) < N;

        const float4* q4 = (const float4*)q;
        float4 q0 = __ldg(&q4[lane]);
        float4 q1 = __ldg(&q4[lane + 32]);
        float4 q2 = __ldg(&q4[lane + 64]);
        float4 q3 = __ldg(&q4[lane + 96]);

        const float4* rowA = (const float4*)(db + (size_t)r0 * D);
        const float4* rowB = (const float4*)(db + (size_t)(r0 + (has1 ? 1 : 0)) * D);

        float4 a0 = __ldcs(&rowA[lane]);
        float4 a1 = __ldcs(&rowA[lane + 32]);
        float4 a2 = __ldcs(&rowA[lane + 64]);
        float4 a3 = __ldcs(&rowA[lane + 96]);
        float4 b0 = __ldcs(&rowB[lane]);
        float4 b1 = __ldcs(&rowB[lane + 32]);
        float4 b2 = __ldcs(&rowB[lane + 64]);
        float4 b3 = __ldcs(&rowB[lane + 96]);

        float dotA = a0.x*q0.x + a0.y*q0.y + a0.z*q0.z + a0.w*q0.w
                   + a1.x*q1.x + a1.y*q1.y + a1.z*q1.z + a1.w*q1.w
                   + a2.x*q2.x + a2.y*q2.y + a2.z*q2.z + a2.w*q2.w
                   + a3.x*q3.x + a3.y*q3.y + a3.z*q3.z + a3.w*q3.w;
        float n2A  = a0.x*a0.x + a0.y*a0.y + a0.z*a0.z + a0.w*a0.w
                   + a1.x*a1.x + a1.y*a1.y + a1.z*a1.z + a1.w*a1.w
                   + a2.x*a2.x + a2.y*a2.y + a2.z*a2.z + a2.w*a2.w
                   + a3.x*a3.x + a3.y*a3.y + a3.z*a3.z + a3.w*a3.w;
        float dotB = b0.x*q0.x + b0.y*q0.y + b0.z*q0.z + b0.w*q0.w
                   + b1.x*q1.x + b1.y*q1.y + b1.z*q1.z + b1.w*q1.w
                   + b2.x*q2.x + b2.y*q2.y + b2.z*q2.z + b2.w*q2.w
                   + b3.x*q3.x + b3.y*q3.y + b3.z*q3.z + b3.w*q3.w;
        float n2B  = b0.x*b0.x + b0.y*b0.y + b0.z*b0.z + b0.w*b0.w
                   + b1.x*b1.x + b1.y*b1.y + b1.z*b1.z + b1.w*b1.w
                   + b2.x*b2.x + b2.y*b2.y + b2.z*b2.z + b2.w*b2.w
                   + b3.x*b3.x + b3.y*b3.y + b3.z*b3.z + b3.w*b3.w;
        float n2Q  = q0.x*q0.x + q0.y*q0.y + q0.z*q0.z + q0.w*q0.w
                   + q1.x*q1.x + q1.y*q1.y + q1.z*q1.z + q1.w*q1.w
                   + q2.x*q2.x + q2.y*q2.y + q2.z*q2.z + q2.w*q2.w
                   + q3.x*q3.x + q3.y*q3.y + q3.z*q3.z + q3.w*q3.w;

#pragma unroll
        for (int off = 16; off; off >>= 1) {
            dotA += __shfl_down_sync(0xFFFFFFFFu, dotA, off);
            n2A  += __shfl_down_sync(0xFFFFFFFFu, n2A, off);
            dotB += __shfl_down_sync(0xFFFFFFFFu, dotB, off);
            n2B  += __shfl_down_sync(0xFFFFFFFFu, n2B, off);
            n2Q  += __shfl_down_sync(0xFFFFFFFFu, n2Q, off);
        }
        if (lane == 0) {
            unsigned int t0key = f2key(T0 * sqrtf(n2Q));
            unsigned int kA = f2key(dotA / fmaxf(sqrtf(n2A), 1e-8f));
            g_keys[r0] = kA;
            if (kA > t0key) {
                unsigned int p = atomicAdd(&g_ncand, 1u);
                if (p < CAND_CAP) { g_cand_key[p] = kA; g_cand_idx[p] = (unsigned int)r0; }
            }
            if (has1) {
                unsigned int kB = f2key(dotB / fmaxf(sqrtf(n2B), 1e-8f));
                g_keys[r0 + 1] = kB;
                if (kB > t0key) {
                    unsigned int p = atomicAdd(&g_ncand, 1u);
                    if (p < CAND_CAP) { g_cand_key[p] = kB; g_cand_idx[p] = (unsigned int)(r0 + 1); }
                }
            }
        }
    }

    // ======================= last-block epilogue ===========================
    __shared__ bool lastb;
    __threadfence();
    __syncthreads();
    if (t == 0) lastb = (atomicAdd(&g_done, 1u) == gridDim.x - 1);
    __syncthreads();
    if (!lastb) return;

    __shared__ unsigned int hist[2048];            // 8KB
    __shared__ unsigned long long lst[LST_CAP];    // 8KB
    __shared__ unsigned int wsum[8];
    __shared__ unsigned int s_sel, scnt;
    __shared__ float qs[8];
    __shared__ float qinv;

    for (int i = t; i < 2048; i += 256) hist[i] = 0;
    if (t == 0) scnt = 0;
    __syncthreads();

    unsigned int n = g_ncand;
    bool fast = (n >= (unsigned int)K && n <= CAND_CAP);

    // ---- phase 1: histogram ----
    if (fast) {
        for (unsigned int i = t; i < n; i += 256)
            atomicAdd(&hist[g_cand_key[i] >> 21], 1u);
    } else {
        int n4 = N >> 2;
        const uint4* k4 = (const uint4*)g_keys;
        for (int i = t; i < n4; i += 256) {
            uint4 k = k4[i];
            atomicAdd(&hist[k.x >> 21], 1u);
            atomicAdd(&hist[k.y >> 21], 1u);
            atomicAdd(&hist[k.z >> 21], 1u);
            atomicAdd(&hist[k.w >> 21], 1u);
        }
        for (int i = (n4 << 2) + t; i < N; i += 256)
            atomicAdd(&hist[g_keys[i] >> 21], 1u);
    }
    __syncthreads();

    // ---- phase 2: threshold scan, thread t owns 8 descending bins ----
    {
        int base = 2047 - t * 8;
        unsigned int c[8];
        unsigned int s = 0;
#pragma unroll
        for (int j = 0; j < 8; j++) { c[j] = hist[base - j]; s += c[j]; }
        int w = t >> 5;
        unsigned int incl = s;
#pragma unroll
        for (int off = 1; off < 32; off <<= 1) {
            unsigned int v = __shfl_up_sync(0xFFFFFFFFu, incl, off);
            if (lane >= off) incl += v;
        }
        if (lane == 31) wsum[w] = incl;
        __syncthreads();
        if (t < 8) {
            unsigned int v = wsum[t];
#pragma unroll
            for (int off = 1; off < 8; off <<= 1) {
                unsigned int u = __shfl_up_sync(0xFFu, v, off);
                if (t >= off) v += u;
            }
            wsum[t] = v;
        }
        __syncthreads();
        unsigned int before = incl - s + (w > 0 ? wsum[w - 1] : 0u);
        unsigned int need = (unsigned int)K;
        if (before < need && before + s >= need) {
            unsigned int cum = before;
#pragma unroll
            for (int j = 0; j < 8; j++) {
                cum += c[j];
                if (cum >= need) { s_sel = (unsigned int)(base - j); break; }
            }
        }
        __syncthreads();
    }
    unsigned int sel = s_sel;

    // ---- fallback only: recollect candidates from g_keys ----
    if (!fast) {
        if (t == 0) g_fcnt = 0;
        __syncthreads();
        for (int i = t; i < N; i += 256) {
            unsigned int key = g_keys[i];
            if ((key >> 21) >= sel) {
                unsigned int p = atomicAdd(&g_fcnt, 1u);
                if (p < CAND_CAP) { g_cand_key[p] = key; g_cand_idx[p] = (unsigned int)i; }
            }
        }
        __syncthreads();
        n = g_fcnt < CAND_CAP ? g_fcnt : CAND_CAP;
    }

    // ---- qinv = 1/|q| ----
    {
        float acc = 0.f;
        for (int i = t; i < D; i += 256) { float v = q[i]; acc += v * v; }
#pragma unroll
        for (int off = 16; off; off >>= 1)
            acc += __shfl_down_sync(0xFFFFFFFFu, acc, off);
        if (lane == 0) qs[t >> 5] = acc;
        __syncthreads();
        if (t == 0) {
            float s = 0.f;
#pragma unroll
            for (int i = 0; i < 8; i++) s += qs[i];
            qinv = 1.0f / fmaxf(sqrtf(s), 1e-8f);
        }
        __syncthreads();
    }

    // ---- phase 3: compact candidates with bin >= sel into smem ----
    for (unsigned int i = t; i < n; i += 256) {
        unsigned int key = g_cand_key[i];
        if ((key >> 21) >= sel) {
            unsigned int p = atomicAdd(&scnt, 1u);
            if (p < LST_CAP)
                lst[p] = ((unsigned long long)key << 32)
                       | (unsigned long long)(~g_cand_idx[i]);
        }
    }
    __syncthreads();
    unsigned int m = scnt;

    // ---- phase 4: exact rank + write (tie-break lower idx via ~idx) ----
    if (m <= LST_CAP) {
        for (unsigned int c = t; c < m; c += 256) {
            unsigned long long me = lst[c];
            unsigned int rank = 0;
            for (unsigned int j = 0; j < m; j++)
                if (lst[j] > me) rank++;
            if (rank < (unsigned int)K) {
                out[rank]     = key2f((unsigned int)(me >> 32)) * qinv;
                out[K + rank] = (float)(~(unsigned int)me);
            }
        }
    } else {
        // overflow: rank over the global candidate list with the filter
        for (unsigned int c = t; c < n; c += 256) {
            unsigned int key = g_cand_key[c];
            if ((key >> 21) < sel) continue;
            unsigned int idx = g_cand_idx[c];
            unsigned int rank = 0;
            for (unsigned int j = 0; j < n; j++) {
                unsigned int kj = g_cand_key[j];
                if ((kj >> 21) < sel) continue;
                if (kj > key || (kj == key && g_cand_idx[j] < idx)) rank++;
            }
            if (rank < (unsigned int)K) {
                out[rank]     = key2f(key) * qinv;
                out[K + rank] = (float)idx;
            }
        }
    }
    __syncthreads();
    if (t == 0) { g_ncand = 0; g_done = 0; }   // self-clean for replay
}

// ---------------------------------------------------------------------------
extern "C" void kernel_launch(void* const* d_in, const int* in_sizes, int n_in,
                              void* d_out, int out_size) {
    const float* q  = (const float*)d_in[0];
    const float* db = (const float*)d_in[1];
    int N = in_sizes[1] / D;
    int K = out_size / 2;   // values + indices
    float* out = (float*)d_out;

    int blocks = (N + 15) / 16;   // 8 warps, 2 rows/warp
    fused_kernel<<<blocks, 256>>>(db, q, out, N, K);
}